// round 1
// baseline (speedup 1.0000x reference)
#include <cuda_runtime.h>

// Depthwise 1D cross-correlation, 13-tap (2*7-1) kernel shared across rows.
// out[r, l] = sum_{j=0}^{12} kern[j] * x[r, l + j - 6], zero-padded,
// where kern[j] = w[6-j] for j<7 else w[j].
//
// x: (32*512 = 16384 rows, L = 4096). HBM-bound: 512 MB total traffic.

#define KSIZE 7
#define TAPS 13          // 2*KSIZE - 1
#define HALO 6           // KSIZE - 1
#define TILE 1024
#define THREADS 256      // each thread computes TILE/THREADS = 4 outputs

__global__ __launch_bounds__(THREADS)
void dwconv13_kernel(const float* __restrict__ x,
                     const float* __restrict__ w,
                     float* __restrict__ out,
                     int L)
{
    __shared__ float s[TILE + 2 * HALO];

    const int row  = blockIdx.y;
    const int tile = blockIdx.x;
    const int tid  = threadIdx.x;

    const long long rowBase = (long long)row * L;
    const int tileStart = tile * TILE;

    // Cooperative load of tile + halo, zero-padded at row boundaries.
    // smem index i corresponds to global column (tileStart + i - HALO).
    #pragma unroll
    for (int i = tid; i < TILE + 2 * HALO; i += THREADS) {
        int col = tileStart + i - HALO;
        float v = 0.0f;
        if (col >= 0 && col < L)
            v = __ldg(x + rowBase + col);
        s[i] = v;
    }

    // Flip taps into registers: kern[j] = w[6-j] (j<7), w[j] (j>=7)
    float kern[TAPS];
    #pragma unroll
    for (int j = 0; j < KSIZE; j++)     kern[j] = __ldg(w + (KSIZE - 1 - j));
    #pragma unroll
    for (int j = KSIZE; j < TAPS; j++)  kern[j] = __ldg(w + j);

    __syncthreads();

    // Each thread computes 4 consecutive outputs -> one float4 store.
    const int o = tid * 4;  // offset within tile

    float acc0 = 0.f, acc1 = 0.f, acc2 = 0.f, acc3 = 0.f;
    #pragma unroll
    for (int j = 0; j < TAPS; j++) {
        float kj = kern[j];
        acc0 = fmaf(kj, s[o + 0 + j], acc0);
        acc1 = fmaf(kj, s[o + 1 + j], acc1);
        acc2 = fmaf(kj, s[o + 2 + j], acc2);
        acc3 = fmaf(kj, s[o + 3 + j], acc3);
    }

    float4 r = make_float4(acc0, acc1, acc2, acc3);
    *reinterpret_cast<float4*>(out + rowBase + tileStart + o) = r;
}

extern "C" void kernel_launch(void* const* d_in, const int* in_sizes, int n_in,
                              void* d_out, int out_size)
{
    const float* x = (const float*)d_in[0];
    const float* w = (const float*)d_in[1];
    float* out     = (float*)d_out;

    const int L = 4096;
    const int n = in_sizes[0];
    const int rows = n / L;               // 16384
    dim3 grid(L / TILE, rows);            // (4, 16384)
    dwconv13_kernel<<<grid, THREADS>>>(x, w, out, L);
}

// round 3
// speedup vs baseline: 1.6838x; 1.6838x over previous
#include <cuda_runtime.h>

// Depthwise 1D cross-correlation, 13-tap (2*7-1) kernel shared across rows.
// out[r, l] = sum_{j=0}^{12} kern[j] * x[r, l + j - 6], zero-padded,
// where kern[j] = w[6-j] for j<7 else w[j].
//
// x: (32*512 = 16384 rows, L = 4096). HBM floor: 512 MB total traffic.
// R2: vectorized LDS.128 window reads + LDG.128 tile load to unthrottle L1.

#define KSIZE 7
#define TAPS 13          // 2*KSIZE - 1
#define HALO 6           // KSIZE - 1
#define TILE 1024
#define THREADS 256      // each thread computes TILE/THREADS = 4 outputs

__global__ __launch_bounds__(THREADS)
void dwconv13_kernel(const float* __restrict__ x,
                     const float* __restrict__ w,
                     float* __restrict__ out,
                     int L)
{
    // physical layout: s[i] holds column (tileStart + i - HALO)
    // base 16B-aligned; window read for output o starts at physical index o (4-float aligned)
    __shared__ __align__(16) float s[TILE + 2 * HALO + 4];

    const int row  = blockIdx.y;
    const int tile = blockIdx.x;
    const int tid  = threadIdx.x;

    const long long rowBase = (long long)row * L;
    const int tileStart = tile * TILE;
    const int o = tid * 4;   // offset of this thread's 4 outputs within the tile

    // Main tile: one LDG.128 per thread (tile is fully in-bounds; L % TILE == 0)
    float4 mv = *reinterpret_cast<const float4*>(x + rowBase + tileStart + o);
    s[HALO + o + 0] = mv.x;
    s[HALO + o + 1] = mv.y;
    s[HALO + o + 2] = mv.z;
    s[HALO + o + 3] = mv.w;

    // Halo: 12 scalar loads, zero-padded at row boundaries
    if (tid < HALO) {                       // left halo: cols tileStart-6 .. tileStart-1
        int col = tileStart - HALO + tid;
        s[tid] = (col >= 0) ? __ldg(x + rowBase + col) : 0.0f;
    } else if (tid < 2 * HALO) {            // right halo: cols tileStart+TILE .. +TILE+5
        int j   = tid - HALO;
        int col = tileStart + TILE + j;
        s[HALO + TILE + j] = (col < L) ? __ldg(x + rowBase + col) : 0.0f;
    }

    // Flipped taps in registers: kern[j] = w[6-j] (j<7), w[j] (j>=7)
    float kern[TAPS];
    #pragma unroll
    for (int j = 0; j < KSIZE; j++)     kern[j] = __ldg(w + (KSIZE - 1 - j));
    #pragma unroll
    for (int j = KSIZE; j < TAPS; j++)  kern[j] = __ldg(w + j);

    __syncthreads();

    // Window: physical s[o .. o+15] = cols (tileStart+o-6 .. tileStart+o+9).
    // Four aligned LDS.128, then all FMAs register-resident.
    float v[16];
    {
        const float4* sv = reinterpret_cast<const float4*>(s + o);
        float4 a = sv[0], b = sv[1], c = sv[2], d = sv[3];
        v[0]=a.x;  v[1]=a.y;  v[2]=a.z;  v[3]=a.w;
        v[4]=b.x;  v[5]=b.y;  v[6]=b.z;  v[7]=b.w;
        v[8]=c.x;  v[9]=c.y;  v[10]=c.z; v[11]=c.w;
        v[12]=d.x; v[13]=d.y; v[14]=d.z; v[15]=d.w;
    }

    float acc0 = 0.f, acc1 = 0.f, acc2 = 0.f, acc3 = 0.f;
    #pragma unroll
    for (int j = 0; j < TAPS; j++) {
        float kj = kern[j];
        acc0 = fmaf(kj, v[j + 0], acc0);
        acc1 = fmaf(kj, v[j + 1], acc1);
        acc2 = fmaf(kj, v[j + 2], acc2);
        acc3 = fmaf(kj, v[j + 3], acc3);
    }

    *reinterpret_cast<float4*>(out + rowBase + tileStart + o) =
        make_float4(acc0, acc1, acc2, acc3);
}

extern "C" void kernel_launch(void* const* d_in, const int* in_sizes, int n_in,
                              void* d_out, int out_size)
{
    const float* x = (const float*)d_in[0];
    const float* w = (const float*)d_in[1];
    float* out     = (float*)d_out;

    const int L = 4096;
    const int n = in_sizes[0];
    const int rows = n / L;               // 16384
    dim3 grid(L / TILE, rows);            // (4, 16384)
    dwconv13_kernel<<<grid, THREADS>>>(x, w, out, L);
}

// round 7
// speedup vs baseline: 1.8274x; 1.0853x over previous
#include <cuda_runtime.h>

// Depthwise 1D cross-correlation, 13-tap (2*7-1) kernel shared across rows.
// out[r, l] = sum_{j=0}^{12} kern[j] * x[r, l + j - 6], zero-padded.
// kern[j] = w[6-j] for j<7 else w[j].
//
// x: (16384 rows, L=4096) fp32. HBM floor: 512 MB.
// R3: no shared memory. Window via 5 overlapping aligned LDG.128 per thread;
// neighbor overlap served by L1. Cuts L1 wavefronts 40 -> 24 per warp.

#define KSIZE 7
#define TAPS 13
#define LOG2L 12
#define LVAL 4096
#define THREADS 256

__global__ __launch_bounds__(THREADS)
void dwconv13_kernel(const float* __restrict__ x,
                     const float* __restrict__ w,
                     float* __restrict__ out)
{
    const int g = blockIdx.x * THREADS + threadIdx.x;
    const long long oFlat = (long long)g * 4;
    const int col = (int)(oFlat & (LVAL - 1));          // start column within row
    const long long rowBase = oFlat - col;              // flat index of row start

    // Taps, flipped: kern[j] = w[6-j] (j<7), w[j] (j>=7). Vector loads, broadcast.
    float4 w0 = *reinterpret_cast<const float4*>(w + 0);   // w0..w3
    float4 w1 = *reinterpret_cast<const float4*>(w + 4);   // w4..w7
    float4 w2 = *reinterpret_cast<const float4*>(w + 8);   // w8..w11
    float  w12 = __ldg(w + 12);
    float kern[TAPS];
    kern[0] = w1.z;  kern[1] = w1.y;  kern[2] = w1.x;  kern[3] = w0.w;
    kern[4] = w0.z;  kern[5] = w0.y;  kern[6] = w0.x;
    kern[7] = w1.w;  kern[8] = w2.x;  kern[9] = w2.y;  kern[10] = w2.z;
    kern[11] = w2.w; kern[12] = w12;

    // Window: v[t] = x[row, col - 6 + t], t = 0..15 (zero-padded outside row).
    float v[16];

    if (col >= 8 && col <= LVAL - 16) {
        // Fast path: 5 aligned float4 loads fully in-bounds.
        const float* p = x + rowBase + col;
        float4 a = *reinterpret_cast<const float4*>(p - 8);
        float4 b = *reinterpret_cast<const float4*>(p - 4);
        float4 c = *reinterpret_cast<const float4*>(p);
        float4 d = *reinterpret_cast<const float4*>(p + 4);
        float4 e = *reinterpret_cast<const float4*>(p + 8);
        v[0]=a.z;  v[1]=a.w;
        v[2]=b.x;  v[3]=b.y;  v[4]=b.z;  v[5]=b.w;
        v[6]=c.x;  v[7]=c.y;  v[8]=c.z;  v[9]=c.w;
        v[10]=d.x; v[11]=d.y; v[12]=d.z; v[13]=d.w;
        v[14]=e.x; v[15]=e.y;
    } else {
        // Row-edge path: bounds-checked scalar loads (4 threads per row).
        #pragma unroll
        for (int t = 0; t < 16; t++) {
            int cc = col - 6 + t;
            v[t] = (cc >= 0 && cc < LVAL) ? __ldg(x + rowBase + cc) : 0.0f;
        }
    }

    float acc0 = 0.f, acc1 = 0.f, acc2 = 0.f, acc3 = 0.f;
    #pragma unroll
    for (int j = 0; j < TAPS; j++) {
        float kj = kern[j];
        acc0 = fmaf(kj, v[j + 0], acc0);
        acc1 = fmaf(kj, v[j + 1], acc1);
        acc2 = fmaf(kj, v[j + 2], acc2);
        acc3 = fmaf(kj, v[j + 3], acc3);
    }

    *reinterpret_cast<float4*>(out + oFlat) = make_float4(acc0, acc1, acc2, acc3);
}

extern "C" void kernel_launch(void* const* d_in, const int* in_sizes, int n_in,
                              void* d_out, int out_size)
{
    const float* x = (const float*)d_in[0];
    const float* w = (const float*)d_in[1];
    float* out     = (float*)d_out;

    const int n = in_sizes[0];                 // 16384 * 4096
    const int nThreadsTotal = n / 4;           // 4 outputs per thread
    dwconv13_kernel<<<nThreadsTotal / THREADS, THREADS>>>(x, w, out);
}